// round 3
// baseline (speedup 1.0000x reference)
#include <cuda_runtime.h>
#include <cuda_bf16.h>
#include <math.h>

// ---------------- static scratch (no runtime allocation allowed) ----------------
#define MAXN 50000
#define MAXE 800000
#define NEG_SLOPE 0.2f

__device__ __align__(16) float g_h1[MAXN * 128];    // layer1 linear output
__device__ __align__(16) float g_out1[MAXN * 128];  // layer1 GAT output
__device__ __align__(16) float g_h2[MAXN * 40];     // layer2 linear output
__device__ __align__(16) float g_as1[MAXN * 8];
__device__ __align__(16) float g_ad1[MAXN * 8];
__device__ __align__(16) float g_as2[MAXN];
__device__ __align__(16) float g_ad2[MAXN];
__device__ int g_deg[MAXN + 1];
__device__ int g_offs[MAXN + 1];
__device__ int g_cur[MAXN];
__device__ int g_srcs[MAXE + MAXN];   // CSR column (src) indices, grouped by dst

__device__ __forceinline__ float lrelu(float a) { return a > 0.f ? a : NEG_SLOPE * a; }

// ---------------- CSR construction ----------------
__global__ void init_deg_kernel(int N) {
    int i = blockIdx.x * blockDim.x + threadIdx.x;
    if (i < N) g_deg[i] = 1;   // self loop
}

__global__ void hist_kernel(const int* __restrict__ ei, int E, int N) {
    int e = blockIdx.x * blockDim.x + threadIdx.x;
    if (e < E) {
        int d = ei[E + e];
        if (d >= 0 && d < N) atomicAdd(&g_deg[d], 1);
    }
}

// single-block exclusive scan over g_deg -> g_offs, g_cur
__global__ void scan_kernel(int N) {
    __shared__ int sums[1024];
    int t = threadIdx.x;
    int chunk = (N + 1023) / 1024;
    int lo = t * chunk;
    int hi = lo + chunk; if (hi > N) hi = N;
    if (lo > N) lo = N;
    int s = 0;
    for (int i = lo; i < hi; i++) s += g_deg[i];
    sums[t] = s;
    __syncthreads();
    for (int off = 1; off < 1024; off <<= 1) {
        int v = 0;
        if (t >= off) v = sums[t - off];
        __syncthreads();
        sums[t] += v;
        __syncthreads();
    }
    int run = (t > 0) ? sums[t - 1] : 0;
    for (int i = lo; i < hi; i++) {
        g_offs[i] = run;
        g_cur[i] = run;
        run += g_deg[i];
    }
    if (t == 1023) g_offs[N] = sums[1023];
}

__global__ void scatter_kernel(const int* __restrict__ ei, int E, int N) {
    int e = blockIdx.x * blockDim.x + threadIdx.x;
    if (e < E) {
        int d = ei[E + e];
        int s = ei[e];
        if (d >= 0 && d < N && s >= 0 && s < N) {
            int p = atomicAdd(&g_cur[d], 1);
            if (p < MAXE + MAXN) g_srcs[p] = s;
        }
    }
}

__global__ void selfloop_kernel(int N) {
    int i = blockIdx.x * blockDim.x + threadIdx.x;
    if (i < N) {
        int p = atomicAdd(&g_cur[i], 1);
        if (p < MAXE + MAXN) g_srcs[p] = i;
    }
}

// ---------------- layer-1 GEMM: h1 = x @ W1 (Nx128 @ 128x128), packed f32x2 ----
// block tile 128(M) x 128(N), K staged 16. 256 threads, thread tile 8x8.
// Accumulators packed over adjacent M rows (fma.rn.f32x2 — 2 FMA per fma-slot).
// Thread (trow=tid>>4, tcol=tid&15): rows trow*8 + 2mp + {0,1}, cols tcol + 16j.
__global__ void __launch_bounds__(256) gemm1_kernel(const float* __restrict__ X,
                                                    const float* __restrict__ W, int N) {
    __shared__ float  Xs[16][130];     // transposed k-major: Xs[k][m], pad 2
    __shared__ float2 Wd[16][128];     // duplicated weights: (w,w)
    int tid = threadIdx.x;
    int tcol = tid & 15;
    int trow = tid >> 4;
    int block_m = blockIdx.x * 128;

    unsigned long long acc[4][8];
#pragma unroll
    for (int mp = 0; mp < 4; mp++)
#pragma unroll
        for (int j = 0; j < 8; j++) acc[mp][j] = 0ull;

    for (int kk = 0; kk < 128; kk += 16) {
        // fill Xs transposed (128 rows x 16 k): 2 threads per row
        {
            int r = tid >> 1;
            int c = (tid & 1) * 8;
            int gm = block_m + r;
            float4 v0 = make_float4(0.f, 0.f, 0.f, 0.f), v1 = v0;
            if (gm < N) {
                v0 = *(const float4*)&X[gm * 128 + kk + c];
                v1 = *(const float4*)&X[gm * 128 + kk + c + 4];
            }
            Xs[c + 0][r] = v0.x; Xs[c + 1][r] = v0.y; Xs[c + 2][r] = v0.z; Xs[c + 3][r] = v0.w;
            Xs[c + 4][r] = v1.x; Xs[c + 5][r] = v1.y; Xs[c + 6][r] = v1.z; Xs[c + 7][r] = v1.w;
        }
        // fill Wd (16 k x 128 n, duplicated)
#pragma unroll
        for (int rep = 0; rep < 8; rep++) {
            int idx = rep * 256 + tid;
            int k = idx >> 7, n = idx & 127;
            float w = W[(kk + k) * 128 + n];
            Wd[k][n] = make_float2(w, w);
        }
        __syncthreads();
#pragma unroll
        for (int k = 0; k < 16; k++) {
            unsigned long long a[4], b[8];
#pragma unroll
            for (int mp = 0; mp < 4; mp++)
                a[mp] = *(const unsigned long long*)&Xs[k][trow * 8 + mp * 2];
#pragma unroll
            for (int j = 0; j < 8; j++)
                b[j] = *(const unsigned long long*)&Wd[k][tcol + 16 * j];
#pragma unroll
            for (int mp = 0; mp < 4; mp++)
#pragma unroll
                for (int j = 0; j < 8; j++)
                    asm("fma.rn.f32x2 %0, %1, %2, %0;" : "+l"(acc[mp][j]) : "l"(a[mp]), "l"(b[j]));
        }
        __syncthreads();
    }
#pragma unroll
    for (int mp = 0; mp < 4; mp++) {
        int m0 = block_m + trow * 8 + mp * 2;
        if (m0 + 1 < N) {
#pragma unroll
            for (int j = 0; j < 8; j++) {
                float2 p = *(float2*)&acc[mp][j];
                int col = tcol + 16 * j;
                g_h1[m0 * 128 + col] = p.x;
                g_h1[(m0 + 1) * 128 + col] = p.y;
            }
        } else if (m0 < N) {
#pragma unroll
            for (int j = 0; j < 8; j++) {
                float2 p = *(float2*)&acc[mp][j];
                g_h1[m0 * 128 + tcol + 16 * j] = p.x;
            }
        }
    }
}

// ---------------- layer-1 attention scalars ----------------
__global__ void attn1_kernel(const float* __restrict__ att_s, const float* __restrict__ att_d, int N) {
    int idx = blockIdx.x * blockDim.x + threadIdx.x;  // one per (n, head)
    int n = idx >> 3, h = idx & 7;
    if (n >= N) return;
    const float* hp = &g_h1[n * 128 + h * 16];
    float s = 0.f, d = 0.f;
#pragma unroll
    for (int c = 0; c < 16; c += 4) {
        float4 v = *(const float4*)&hp[c];
        float4 a = *(const float4*)&att_s[h * 16 + c];
        float4 b = *(const float4*)&att_d[h * 16 + c];
        s += v.x * a.x + v.y * a.y + v.z * a.z + v.w * a.w;
        d += v.x * b.x + v.y * b.y + v.z * b.z + v.w * b.w;
    }
    g_as1[idx] = s;
    g_ad1[idx] = d;
}

// ---------------- layer-1 aggregation: one warp per dst node ----------------
// lane = (g, u): g = lane>>3 (edge group of 4), u = lane&7 (head; owns 16 chans)
__global__ void agg1_kernel(const float* __restrict__ bias, int N) {
    int gw = (blockIdx.x * blockDim.x + threadIdx.x) >> 5;
    int lane = threadIdx.x & 31;
    int nwarps = (gridDim.x * blockDim.x) >> 5;
    int u = lane & 7;
    int g = lane >> 3;
    for (int i = gw; i < N; i += nwarps) {
        int start = g_offs[i], end = g_offs[i + 1];
        float adh = g_ad1[i * 8 + u];

        // pass A: segment max per head (4-way edge-parallel)
        float mh = -1e30f;
        for (int e = start + g; e < end; e += 4) {
            int s = g_srcs[e];
            mh = fmaxf(mh, lrelu(g_as1[s * 8 + u] + adh));
        }
        mh = fmaxf(mh, __shfl_xor_sync(0xffffffffu, mh, 8));
        mh = fmaxf(mh, __shfl_xor_sync(0xffffffffu, mh, 16));

        // pass B: weighted sum, 4 edges in flight
        float acc[16];
#pragma unroll
        for (int j = 0; j < 16; j++) acc[j] = 0.f;
        float denom = 0.f;
        for (int e = start + g; e < end; e += 4) {
            int s = g_srcs[e];
            float a = lrelu(g_as1[s * 8 + u] + adh);
            float ee = __expf(a - mh);
            denom += ee;
            const float4* hp = (const float4*)&g_h1[s * 128 + u * 16];
            float4 v0 = hp[0], v1 = hp[1], v2 = hp[2], v3 = hp[3];
            acc[0]  = fmaf(ee, v0.x, acc[0]);  acc[1]  = fmaf(ee, v0.y, acc[1]);
            acc[2]  = fmaf(ee, v0.z, acc[2]);  acc[3]  = fmaf(ee, v0.w, acc[3]);
            acc[4]  = fmaf(ee, v1.x, acc[4]);  acc[5]  = fmaf(ee, v1.y, acc[5]);
            acc[6]  = fmaf(ee, v1.z, acc[6]);  acc[7]  = fmaf(ee, v1.w, acc[7]);
            acc[8]  = fmaf(ee, v2.x, acc[8]);  acc[9]  = fmaf(ee, v2.y, acc[9]);
            acc[10] = fmaf(ee, v2.z, acc[10]); acc[11] = fmaf(ee, v2.w, acc[11]);
            acc[12] = fmaf(ee, v3.x, acc[12]); acc[13] = fmaf(ee, v3.y, acc[13]);
            acc[14] = fmaf(ee, v3.z, acc[14]); acc[15] = fmaf(ee, v3.w, acc[15]);
        }
        // reduce over the 4 edge groups (lane bits 3,4)
#pragma unroll
        for (int off = 8; off <= 16; off <<= 1) {
#pragma unroll
            for (int j = 0; j < 16; j++)
                acc[j] += __shfl_xor_sync(0xffffffffu, acc[j], off);
            denom += __shfl_xor_sync(0xffffffffu, denom, off);
        }
        float inv = 1.0f / (denom + 1e-16f);
        // lane (g,u) writes channels u*16 + g*4 .. +3
        int c0 = u * 16 + g * 4;
        float4 bq = *(const float4*)&bias[c0];
        float4 o;
        o.x = acc[g * 4 + 0] * inv + bq.x;
        o.y = acc[g * 4 + 1] * inv + bq.y;
        o.z = acc[g * 4 + 2] * inv + bq.z;
        o.w = acc[g * 4 + 3] * inv + bq.w;
        *(float4*)&g_out1[i * 128 + c0] = o;
    }
}

// ---------------- layer-2 GEMM + attention scalars ----------------
// h2 = out1 @ W2 (Nx128 @ 128x40), fused a_src2/a_dst2. One warp -> 4 nodes.
// k-pair packed f32x2 accumulation (even/odd-k partial sums, merged at end).
__global__ void __launch_bounds__(256) gemm2_kernel(const float* __restrict__ W,
                                                    const float* __restrict__ att_s,
                                                    const float* __restrict__ att_d, int N) {
    __shared__ float WsT[40][130];     // transposed: WsT[n][k], padded
    __shared__ float Xsw[8][4][128];
    int tid = threadIdx.x;
    for (int i = tid; i < 128 * 40; i += 256) {
        int k = i / 40, n = i - k * 40;
        WsT[n][k] = W[i];
    }
    int w = tid >> 5, lane = tid & 31;
    int n0 = (blockIdx.x * 8 + w) * 4;
    __syncthreads();
    if (n0 >= N) return;  // warp-uniform; no further __syncthreads below

#pragma unroll
    for (int r = 0; r < 4; r++) {
        int n = n0 + r;
        float4 v = make_float4(0.f, 0.f, 0.f, 0.f);
        if (n < N) v = *(const float4*)&g_out1[n * 128 + lane * 4];
        *(float4*)&Xsw[w][r][lane * 4] = v;
    }
    __syncwarp();

    unsigned long long acc[4][2];
#pragma unroll
    for (int r = 0; r < 4; r++) { acc[r][0] = 0ull; acc[r][1] = 0ull; }

    bool hi = (lane < 8);
    for (int k = 0; k < 128; k += 2) {
        unsigned long long b0 = *(const unsigned long long*)&WsT[lane][k];
        unsigned long long b1 = hi ? *(const unsigned long long*)&WsT[32 + lane][k] : 0ull;
#pragma unroll
        for (int r = 0; r < 4; r++) {
            unsigned long long a = *(const unsigned long long*)&Xsw[w][r][k];
            asm("fma.rn.f32x2 %0, %1, %2, %0;" : "+l"(acc[r][0]) : "l"(a), "l"(b0));
            asm("fma.rn.f32x2 %0, %1, %2, %0;" : "+l"(acc[r][1]) : "l"(a), "l"(b1));
        }
    }

    float asl = att_s[lane];
    float ash = hi ? att_s[32 + lane] : 0.f;
    float adl = att_d[lane];
    float adh = hi ? att_d[32 + lane] : 0.f;
#pragma unroll
    for (int r = 0; r < 4; r++) {
        int n = n0 + r;
        if (n >= N) break;
        float2 p0 = *(float2*)&acc[r][0];
        float2 p1 = *(float2*)&acc[r][1];
        float s0 = p0.x + p0.y;
        float s1 = p1.x + p1.y;
        g_h2[n * 40 + lane] = s0;
        if (hi) g_h2[n * 40 + 32 + lane] = s1;
        float sa = s0 * asl + s1 * ash;
        float da = s0 * adl + s1 * adh;
#pragma unroll
        for (int off = 16; off; off >>= 1) {
            sa += __shfl_xor_sync(0xffffffffu, sa, off);
            da += __shfl_xor_sync(0xffffffffu, da, off);
        }
        if (lane == 0) { g_as2[n] = sa; g_ad2[n] = da; }
    }
}

// ---------------- layer-2 aggregation: one warp per dst node ----------------
// lane = (g, u): g = lane>>3 (edge group of 4), u = lane&7 (owns 5 channels)
__global__ void agg2_kernel(const float* __restrict__ bias, float* __restrict__ out, int N) {
    int gw = (blockIdx.x * blockDim.x + threadIdx.x) >> 5;
    int lane = threadIdx.x & 31;
    int nwarps = (gridDim.x * blockDim.x) >> 5;
    int u = lane & 7;
    int g = lane >> 3;
    for (int i = gw; i < N; i += nwarps) {
        int start = g_offs[i], end = g_offs[i + 1];
        float adh = g_ad2[i];

        float mh = -1e30f;
        for (int e = start + g; e < end; e += 4) {
            int s = g_srcs[e];
            mh = fmaxf(mh, lrelu(g_as2[s] + adh));
        }
        mh = fmaxf(mh, __shfl_xor_sync(0xffffffffu, mh, 8));
        mh = fmaxf(mh, __shfl_xor_sync(0xffffffffu, mh, 16));

        float acc[5];
#pragma unroll
        for (int j = 0; j < 5; j++) acc[j] = 0.f;
        float denom = 0.f;
        for (int e = start + g; e < end; e += 4) {
            int s = g_srcs[e];
            float a = lrelu(g_as2[s] + adh);
            float ee = __expf(a - mh);
            denom += ee;
            const float* hp = &g_h2[s * 40 + u * 5];
#pragma unroll
            for (int j = 0; j < 5; j++) acc[j] = fmaf(ee, hp[j], acc[j]);
        }
#pragma unroll
        for (int off = 8; off <= 16; off <<= 1) {
#pragma unroll
            for (int j = 0; j < 5; j++)
                acc[j] += __shfl_xor_sync(0xffffffffu, acc[j], off);
            denom += __shfl_xor_sync(0xffffffffu, denom, off);
        }
        if (g == 0) {
            float inv = 1.0f / (denom + 1e-16f);
#pragma unroll
            for (int j = 0; j < 5; j++)
                out[i * 40 + u * 5 + j] = acc[j] * inv + bias[u * 5 + j];
        }
    }
}

// ---------------- launch ----------------
extern "C" void kernel_launch(void* const* d_in, const int* in_sizes, int n_in,
                              void* d_out, int out_size) {
    const float* x   = (const float*)d_in[0];
    const int*   ei  = (const int*)d_in[1];   // jax downcasts int64 -> int32 (x64 disabled)
    const float* W1  = (const float*)d_in[2];
    const float* as1 = (const float*)d_in[3];
    const float* ad1 = (const float*)d_in[4];
    const float* b1  = (const float*)d_in[5];
    const float* W2  = (const float*)d_in[6];
    const float* as2 = (const float*)d_in[7];
    const float* ad2 = (const float*)d_in[8];
    const float* b2  = (const float*)d_in[9];
    float* out = (float*)d_out;

    int N = in_sizes[0] / 128;
    int E = in_sizes[1] / 2;
    if (N > MAXN) N = MAXN;
    if (E > MAXE) E = MAXE;

    // CSR build (shared by both layers)
    init_deg_kernel<<<(N + 255) / 256, 256>>>(N);
    hist_kernel<<<(E + 255) / 256, 256>>>(ei, E, N);
    scan_kernel<<<1, 1024>>>(N);
    scatter_kernel<<<(E + 255) / 256, 256>>>(ei, E, N);
    selfloop_kernel<<<(N + 255) / 256, 256>>>(N);

    // layer 1
    gemm1_kernel<<<(N + 127) / 128, 256>>>(x, W1, N);
    attn1_kernel<<<(N * 8 + 255) / 256, 256>>>(as1, ad1, N);
    agg1_kernel<<<(N + 7) / 8, 256>>>(b1, N);

    // layer 2
    gemm2_kernel<<<(((N + 3) / 4) + 7) / 8, 256>>>(W2, as2, ad2, N);
    agg2_kernel<<<(N + 7) / 8, 256>>>(b2, out, N);
}